// round 6
// baseline (speedup 1.0000x reference)
#include <cuda_runtime.h>

// CapsuleLayer collapse: routing softmax over a singleton axis is identically 1,
// so out = squash( s ),  s[b,j,k] = sum_{i,u} W[i,j,k,u] * x[b,u,i].
// GEMM: C[32 x 1024] = A[32 x 32768] * B[32768 x 1024], K = (i,u).

#define N_B    32
#define N_IU   16
#define N_IC   2048
#define N_NU   16
#define N_US   64
#define N_N    (N_NU * N_US)   // 1024
#define IC_PER 32              // i's per GEMM block
#define N_ICCH (N_IC / IC_PER) // 64 K-split chunks
#define WS_STR 258             // padded smem row stride (even, bank-conflict-free)

// Scratch (no allocation allowed)
__device__ float g_xT[N_IC * N_IU * N_B];        // [i][u][b]  4 MB
__device__ float g_part[N_ICCH][N_B][N_N];       // 8 MB K-split partials

typedef unsigned long long ull;

__device__ __forceinline__ ull fma2(ull a, ull b, ull c) {
    ull d;
    asm("fma.rn.f32x2 %0, %1, %2, %3;" : "=l"(d) : "l"(a), "l"(b), "l"(c));
    return d;
}
__device__ __forceinline__ ull dup2(float x) {
    ull d;
    asm("mov.b64 %0, {%1, %1};" : "=l"(d) : "f"(x));
    return d;
}

// ---------------------------------------------------------------------------
// Kernel 1: x[b][u][i] -> xT[i][u][b].  grid (16 i-tiles of 128, 16 u),
// block (32,32).  float4 reads along i; conflict-free column reads on write.
// ---------------------------------------------------------------------------
__global__ void transpose_x_kernel(const float* __restrict__ x) {
    __shared__ float tile[128][33];
    const int i0 = blockIdx.x * 128;
    const int u  = blockIdx.y;
    const int tx = threadIdx.x, ty = threadIdx.y;   // ty = b on read, row-group on write

    const float4 v = *reinterpret_cast<const float4*>(
        x + (size_t)ty * (N_IU * N_IC) + (size_t)u * N_IC + i0 + 4 * tx);
    tile[4 * tx + 0][ty] = v.x;
    tile[4 * tx + 1][ty] = v.y;
    tile[4 * tx + 2][ty] = v.z;
    tile[4 * tx + 3][ty] = v.w;
    __syncthreads();

    #pragma unroll
    for (int rr = 0; rr < 4; rr++) {
        const int row = rr * 32 + ty;               // local i
        g_xT[(size_t)(i0 + row) * (N_IU * N_B) + u * N_B + tx] = tile[row][tx];
    }
}

// ---------------------------------------------------------------------------
// Kernel 2: K-split GEMM partials, packed f32x2 FMAs.
// grid (64 ic, 4 jq), 256 threads, 2 CTAs/SM.
// Block tile: M=32 (all b), N=256 (4 j), K-chunk = 32 i * 16 u = 512.
// Stage = 1 i (16 u-rows), double-buffered smem, register prefetch.
// Thread micro-tile: 4 m  x  8 n  (4 groups g, one n-pair each).
// ---------------------------------------------------------------------------
__global__ void __launch_bounds__(256, 2) gemm_part_kernel(const float* __restrict__ W) {
    __shared__ float Ws[2][16 * WS_STR];   // [u][n] (n padded stride 258)
    __shared__ float Xs[2][16 * 32];       // [u][b]

    const int t  = threadIdx.x;
    const int ic = blockIdx.x;             // i in [ic*32, ic*32+32)
    const int jq = blockIdx.y;             // n in [jq*256, jq*256+256)
    const int tn = t & 31;                 // n-pair id (32)
    const int tm = t >> 5;                 // m-group (8)
    const int lk = t >> 2;                 // loader: k index (0..63)
    const int lu = 4 * (t & 3);            // loader: first u of the float4

    const float* Wg = W + (size_t)(ic * IC_PER) * 16384 + (size_t)jq * 4096 + 4 * t;
    const float* Xg = g_xT + (size_t)(ic * IC_PER) * (N_IU * N_B) + 4 * t;

    ull acc[4][4];
    #pragma unroll
    for (int m = 0; m < 4; m++)
        #pragma unroll
        for (int g = 0; g < 4; g++) acc[m][g] = 0ULL;

    float4 wreg[4];
    float4 xreg;

    auto load_regs = [&](int s) {
        const float* wb = Wg + (size_t)s * 16384;
        #pragma unroll
        for (int jL = 0; jL < 4; jL++)
            wreg[jL] = *reinterpret_cast<const float4*>(wb + jL * 1024);
        if (t < 128)
            xreg = *reinterpret_cast<const float4*>(Xg + s * (N_IU * N_B));
    };
    auto store_regs = [&](int buf) {
        float* WsB = Ws[buf];
        #pragma unroll
        for (int jL = 0; jL < 4; jL++) {
            const float4 v = wreg[jL];
            const int col = jL * 64 + lk;
            WsB[(lu + 0) * WS_STR + col] = v.x;   // banks: (2u + k) % 32 -> all distinct
            WsB[(lu + 1) * WS_STR + col] = v.y;
            WsB[(lu + 2) * WS_STR + col] = v.z;
            WsB[(lu + 3) * WS_STR + col] = v.w;
        }
        if (t < 128)
            *reinterpret_cast<float4*>(Xs[buf] + 4 * t) = xreg;
    };
    auto compute = [&](int buf) {
        const float* WsB = Ws[buf];
        const float* XsB = Xs[buf];
        #pragma unroll
        for (int r = 0; r < 16; r++) {
            const float4 a4 = *reinterpret_cast<const float4*>(XsB + r * 32 + tm * 4);
            ull ad[4];
            ad[0] = dup2(a4.x); ad[1] = dup2(a4.y); ad[2] = dup2(a4.z); ad[3] = dup2(a4.w);
            #pragma unroll
            for (int g = 0; g < 4; g++) {
                // packed n-pair straight from smem: LDS.64, no repack movs
                const ull w = *reinterpret_cast<const ull*>(WsB + r * WS_STR + g * 64 + 2 * tn);
                #pragma unroll
                for (int m = 0; m < 4; m++)
                    acc[m][g] = fma2(ad[m], w, acc[m][g]);
            }
        }
    };

    load_regs(0);
    store_regs(0);
    __syncthreads();

    #pragma unroll 1
    for (int s = 0; s < IC_PER; s++) {
        const int cur = s & 1;
        if (s + 1 < IC_PER) load_regs(s + 1);   // next-stage LDGs in flight
        compute(cur);
        if (s + 1 < IC_PER) {
            store_regs(cur ^ 1);
            __syncthreads();
        }
    }

    // epilogue: deterministic partials (float2 = one n-pair per store)
    float* outp = &g_part[ic][0][0];
    #pragma unroll
    for (int m = 0; m < 4; m++) {
        const int bb = tm * 4 + m;
        #pragma unroll
        for (int g = 0; g < 4; g++) {
            union { ull u; float2 f; } c; c.u = acc[m][g];
            *reinterpret_cast<float2*>(outp + (size_t)bb * N_N + jq * 256 + g * 64 + 2 * tn) = c.f;
        }
    }
}

// ---------------------------------------------------------------------------
// Kernel 3: sum K-split partials + squash.
//   msq[b,k] = sum_j s[b,j,k]^2 ;  out = s * msq / ((1+msq) * sqrt(msq))
// grid (32 b, 2 k-halves), block 512 (warp = j, lane = k within half).
// ---------------------------------------------------------------------------
__global__ void reduce_squash_kernel(float* __restrict__ out) {
    __shared__ float sm[512];
    __shared__ float msq[32];
    const int b  = blockIdx.x;
    const int kh = blockIdx.y;
    const int t  = threadIdx.x;
    const int j  = t >> 5;
    const int kl = t & 31;
    const int n  = j * N_US + kh * 32 + kl;

    float s = 0.0f;
    #pragma unroll
    for (int ic = 0; ic < N_ICCH; ic++)
        s += g_part[ic][b][n];

    sm[t] = s;
    __syncthreads();
    if (t < 32) {
        float m = 0.0f;
        #pragma unroll
        for (int jj = 0; jj < N_NU; jj++) {
            const float v = sm[jj * 32 + t];
            m += v * v;
        }
        msq[t] = m;
    }
    __syncthreads();
    const float m = msq[kl];
    out[(size_t)b * N_N + n] = s * m / ((1.0f + m) * sqrtf(m));
}

// ---------------------------------------------------------------------------
extern "C" void kernel_launch(void* const* d_in, const int* in_sizes, int n_in,
                              void* d_out, int out_size) {
    const float* x = (const float*)d_in[0];
    const float* W = (const float*)d_in[1];
    if (n_in >= 2 && in_sizes[0] > in_sizes[1]) {   // safety: x is the smaller input
        x = (const float*)d_in[1];
        W = (const float*)d_in[0];
    }
    transpose_x_kernel<<<dim3(N_IC / 128, N_IU), dim3(32, 32)>>>(x);
    gemm_part_kernel<<<dim3(N_ICCH, 4), 256>>>(W);
    reduce_squash_kernel<<<dim3(N_B, 2), 512>>>((float*)d_out);
}

// round 7
// speedup vs baseline: 1.6341x; 1.6341x over previous
#include <cuda_runtime.h>

// CapsuleLayer collapse: routing softmax over a singleton axis is identically 1,
// so out = squash( s ),  s[b,j,k] = sum_{i,u} W[i,j,k,u] * x[b,u,i].
// GEMM: C[32 x 1024] = A[32 x 32768] * B[32768 x 1024], K = (i,u).
//
// Key shape fact: M = 32 fits in ONE thread's accumulators as 16 f32x2 b-pairs.
// => each W element is smem-read by exactly one thread (LDS traffic = 134 MB total),
//    x is warp-uniform broadcast. GEMM is pure fma-pipe-bound (~31 us floor).

#define N_B    32
#define N_IU   16
#define N_IC   2048
#define N_N    1024
#define IC_PER 16              // i's per GEMM block (stages)
#define N_ICCH (N_IC / IC_PER) // 128 K-split chunks
#define S_STG  IC_PER

// Scratch (no allocation allowed)
__device__ float g_xT[N_IC * N_IU * N_B];        // [i][u][b]  4 MB
__device__ float g_part[N_ICCH][N_B][N_N];       // 16 MB K-split partials

typedef unsigned long long ull;

__device__ __forceinline__ ull fma2(ull a, ull b, ull c) {
    ull d;
    asm("fma.rn.f32x2 %0, %1, %2, %3;" : "=l"(d) : "l"(a), "l"(b), "l"(c));
    return d;
}
__device__ __forceinline__ ull dup2(float x) {
    ull d;
    asm("mov.b64 %0, {%1, %1};" : "=l"(d) : "f"(x));
    return d;
}
__device__ __forceinline__ unsigned su32(const void* p) {
    return (unsigned)__cvta_generic_to_shared(p);
}
__device__ __forceinline__ void cp16(unsigned dst, const void* src) {
    asm volatile("cp.async.cg.shared.global [%0], [%1], 16;" :: "r"(dst), "l"(src));
}

// ---------------------------------------------------------------------------
// Kernel 1: x[b][u][i] -> xT[i][u][b].  grid (16 i-tiles of 128, 8 u-pairs),
// block (32,32).  2 independent LDG.128 per thread (MLP), conflict-free tiles.
// ---------------------------------------------------------------------------
__global__ void transpose_x_kernel(const float* __restrict__ x) {
    __shared__ float tile[2][128][33];
    const int i0 = blockIdx.x * 128;
    const int u0 = blockIdx.y * 2;
    const int tx = threadIdx.x, ty = threadIdx.y;   // ty = b on read

    const float4 v0 = *reinterpret_cast<const float4*>(
        x + (size_t)ty * (N_IU * N_IC) + (size_t)u0 * N_IC + i0 + 4 * tx);
    const float4 v1 = *reinterpret_cast<const float4*>(
        x + (size_t)ty * (N_IU * N_IC) + (size_t)(u0 + 1) * N_IC + i0 + 4 * tx);
    tile[0][4 * tx + 0][ty] = v0.x;  tile[0][4 * tx + 1][ty] = v0.y;
    tile[0][4 * tx + 2][ty] = v0.z;  tile[0][4 * tx + 3][ty] = v0.w;
    tile[1][4 * tx + 0][ty] = v1.x;  tile[1][4 * tx + 1][ty] = v1.y;
    tile[1][4 * tx + 2][ty] = v1.z;  tile[1][4 * tx + 3][ty] = v1.w;
    __syncthreads();

    #pragma unroll
    for (int rr = 0; rr < 4; rr++) {
        const int row = rr * 32 + ty;               // local i
        g_xT[(size_t)(i0 + row) * (N_IU * N_B) + u0 * N_B + tx]       = tile[0][row][tx];
        g_xT[(size_t)(i0 + row) * (N_IU * N_B) + (u0 + 1) * N_B + tx] = tile[1][row][tx];
    }
}

// ---------------------------------------------------------------------------
// Kernel 2: K-split GEMM, b-pair-packed f32x2 FMAs, cp.async triple buffer.
// grid (128 ic, 4 jq), 128 threads, 4 CTAs/SM.
// Block tile: M=32 (all b, in-regs), N=256, K-chunk = 16 i * 16 u = 256.
// Thread: 2 n-columns (t and t+128), 16 b-pair accs each = 64 acc regs.
// Smem W stays in verbatim global [n][u] layout (no transpose, no scatter).
// ---------------------------------------------------------------------------
#define WS_F 4096                       // 256 n * 16 u floats per stage
#define XS_F 512                        // 16 u * 32 b floats per stage
#define GEMM_SMEM_BYTES ((3 * WS_F + 3 * XS_F) * 4)   // 55296 B

__global__ void __launch_bounds__(128, 4) gemm_part_kernel(const float* __restrict__ W) {
    extern __shared__ float sm[];
    float* Wsm = sm;                    // 3 stage buffers
    float* Xsm = sm + 3 * WS_F;

    const int t  = threadIdx.x;
    const int ic = blockIdx.x;
    const int jq = blockIdx.y;

    const float* Wbase = W    + (size_t)ic * IC_PER * 16384 + (size_t)jq * 4096;
    const float* Xbase = g_xT + (size_t)ic * IC_PER * (N_IU * N_B);

    ull acc0[16], acc1[16];
    #pragma unroll
    for (int p = 0; p < 16; p++) { acc0[p] = 0ULL; acc1[p] = 0ULL; }

    auto issue = [&](int s) {
        const int buf = s % 3;
        const float* wg = Wbase + (size_t)s * 16384;
        float* wd = Wsm + buf * WS_F;
        #pragma unroll
        for (int p = 0; p < 8; p++)
            cp16(su32(wd + p * 512 + t * 4), wg + p * 512 + t * 4);
        cp16(su32(Xsm + buf * XS_F + t * 4), Xbase + s * XS_F + t * 4);
        asm volatile("cp.async.commit_group;");
    };

    issue(0);
    issue(1);

    #pragma unroll 1
    for (int s = 0; s < S_STG; s++) {
        if (s < S_STG - 1) asm volatile("cp.async.wait_group 1;");
        else               asm volatile("cp.async.wait_group 0;");
        __syncthreads();

        const int buf = s % 3;
        const float* WsB = Wsm + buf * WS_F;
        const float* XsB = Xsm + buf * XS_F;

        #pragma unroll
        for (int r4 = 0; r4 < 4; r4++) {
            // this thread's two n-columns, 4 u's each (one LDS.128 apiece)
            const float4 w0 = *reinterpret_cast<const float4*>(WsB + t * 16 + r4 * 4);
            const float4 w1 = *reinterpret_cast<const float4*>(WsB + (t + 128) * 16 + r4 * 4);
            const float wa0[4] = {w0.x, w0.y, w0.z, w0.w};
            const float wa1[4] = {w1.x, w1.y, w1.z, w1.w};
            #pragma unroll
            for (int q = 0; q < 4; q++) {
                const int r = r4 * 4 + q;                 // u index
                const ull wd0 = dup2(wa0[q]);
                const ull wd1 = dup2(wa1[q]);
                #pragma unroll
                for (int h = 0; h < 8; h++) {             // 4 b's per iter
                    const ulonglong2 xv = *reinterpret_cast<const ulonglong2*>(XsB + r * 32 + h * 4);
                    acc0[2 * h]     = fma2(xv.x, wd0, acc0[2 * h]);
                    acc0[2 * h + 1] = fma2(xv.y, wd0, acc0[2 * h + 1]);
                    acc1[2 * h]     = fma2(xv.x, wd1, acc1[2 * h]);
                    acc1[2 * h + 1] = fma2(xv.y, wd1, acc1[2 * h + 1]);
                }
            }
        }
        if (s + 2 < S_STG) issue(s + 2);   // all threads passed this iter's barrier,
                                           // so buf (s+2)%3 == (s-1)%3 is free
    }

    // epilogue: deterministic partials, coalesced scalar rows (lanes span n)
    float* outp = &g_part[ic][0][jq * 256];
    #pragma unroll
    for (int bp = 0; bp < 16; bp++) {
        union { ull u; float2 f; } c0, c1;
        c0.u = acc0[bp]; c1.u = acc1[bp];
        outp[(size_t)(2 * bp)     * N_N + t]       = c0.f.x;
        outp[(size_t)(2 * bp + 1) * N_N + t]       = c0.f.y;
        outp[(size_t)(2 * bp)     * N_N + 128 + t] = c1.f.x;
        outp[(size_t)(2 * bp + 1) * N_N + 128 + t] = c1.f.y;
    }
}

// ---------------------------------------------------------------------------
// Kernel 3: sum 128 K-split partials + squash.
//   msq[b,k] = sum_j s[b,j,k]^2 ;  out = s * msq / ((1+msq) * sqrt(msq))
// grid (32 b, 4 k-quarters), block 256: t = j*16 + kl.
// ---------------------------------------------------------------------------
__global__ void reduce_squash_kernel(float* __restrict__ out) {
    __shared__ float smv[256];
    __shared__ float msq[16];
    const int b  = blockIdx.x;
    const int kq = blockIdx.y;
    const int t  = threadIdx.x;
    const int j  = t >> 4;
    const int kl = t & 15;
    const int n  = j * 64 + kq * 16 + kl;

    float s = 0.0f;
    #pragma unroll 8
    for (int ic = 0; ic < N_ICCH; ic++)
        s += g_part[ic][b][n];

    smv[t] = s;
    __syncthreads();
    if (t < 16) {
        float m = 0.0f;
        #pragma unroll
        for (int jj = 0; jj < 16; jj++) {
            const float v = smv[jj * 16 + t];
            m += v * v;
        }
        msq[t] = m;
    }
    __syncthreads();
    const float m = msq[kl];
    out[(size_t)b * N_N + n] = s * m / ((1.0f + m) * sqrtf(m));
}

// ---------------------------------------------------------------------------
extern "C" void kernel_launch(void* const* d_in, const int* in_sizes, int n_in,
                              void* d_out, int out_size) {
    const float* x = (const float*)d_in[0];
    const float* W = (const float*)d_in[1];
    if (n_in >= 2 && in_sizes[0] > in_sizes[1]) {   // safety: x is the smaller input
        x = (const float*)d_in[1];
        W = (const float*)d_in[0];
    }
    cudaFuncSetAttribute(gemm_part_kernel,
                         cudaFuncAttributeMaxDynamicSharedMemorySize, GEMM_SMEM_BYTES);
    transpose_x_kernel<<<dim3(N_IC / 128, N_IU / 2), dim3(32, 32)>>>(x);
    gemm_part_kernel<<<dim3(N_ICCH, 4), 128, GEMM_SMEM_BYTES>>>(W);
    reduce_squash_kernel<<<dim3(N_B, 4), 256>>>((float*)d_out);
}

// round 11
// speedup vs baseline: 1.7862x; 1.0930x over previous
#include <cuda_runtime.h>

// CapsuleLayer collapse: routing softmax over a singleton axis is identically 1,
// so out = squash( s ),  s[b,j,k] = sum_{i,u} W[i,j,k,u] * x[b,u,i].
// GEMM: C[32 x 1024] = A[32 x 32768] * B[32768 x 1024], K = (i,u).
//
// M = 32 lives entirely in ONE thread's accumulators as 16 f32x2 b-pairs:
// each W element is smem-read by exactly one thread, x reads are warp-broadcast.
// R8 fix: 16B-granule swizzle of the W smem layout. The verbatim layout gave
// lane stride 64B => 16-way LDS bank conflicts; swizzled layout hits the
// 4-cycle crossbar floor.

#define N_B    32
#define N_IU   16
#define N_IC   2048
#define N_N    1024
#define IC_PER 16              // i's per GEMM block (stages)
#define N_ICCH (N_IC / IC_PER) // 128 K-split chunks
#define S_STG  IC_PER

// Scratch (no allocation allowed)
__device__ float g_xT[N_IC * N_IU * N_B];        // [i][u][b]  4 MB
__device__ float g_part[N_ICCH][N_B][N_N];       // 16 MB K-split partials

typedef unsigned long long ull;

__device__ __forceinline__ ull fma2(ull a, ull b, ull c) {
    ull d;
    asm("fma.rn.f32x2 %0, %1, %2, %3;" : "=l"(d) : "l"(a), "l"(b), "l"(c));
    return d;
}
__device__ __forceinline__ ull dup2(float x) {
    ull d;
    asm("mov.b64 %0, {%1, %1};" : "=l"(d) : "f"(x));
    return d;
}
__device__ __forceinline__ unsigned su32(const void* p) {
    return (unsigned)__cvta_generic_to_shared(p);
}
__device__ __forceinline__ void cp16(unsigned dst, const void* src) {
    asm volatile("cp.async.cg.shared.global [%0], [%1], 16;" :: "r"(dst), "l"(src));
}

// ---------------------------------------------------------------------------
// Kernel 1: x[b][u][i] -> xT[i][u][b].
// grid (64 i-tiles of 32, 16 u) = 1024 blocks, block (32,8) = 256 thr.
// Coalesced reads along i, coalesced writes along b, conflict-free smem.
// ---------------------------------------------------------------------------
__global__ void __launch_bounds__(256) transpose_x_kernel(const float* __restrict__ x) {
    __shared__ float tile[32][33];
    const int i0 = blockIdx.x * 32;
    const int u  = blockIdx.y;
    const int tx = threadIdx.x, ty = threadIdx.y;

    #pragma unroll
    for (int k = 0; k < 4; k++) {
        const int b = ty + 8 * k;
        tile[b][tx] = x[(size_t)b * (N_IU * N_IC) + (size_t)u * N_IC + i0 + tx];
    }
    __syncthreads();
    #pragma unroll
    for (int k = 0; k < 4; k++) {
        const int row = ty + 8 * k;     // local i
        g_xT[(size_t)(i0 + row) * (N_IU * N_B) + u * N_B + tx] = tile[tx][row];
    }
}

// ---------------------------------------------------------------------------
// Kernel 2: K-split GEMM, b-pair-packed f32x2 FMAs, cp.async triple buffer.
// grid (128 ic, 4 jq), 128 threads, 4 CTAs/SM.
// Block tile: M=32 (all b, in-regs), N=256, K-chunk = 16 i * 16 u = 256.
// Thread: 2 n-columns (t and t+128), 16 b-pair accs each = 64 acc regs.
// W smem: row n holds its four 16B granules at slots (g + (n>>1)) & 3.
// ---------------------------------------------------------------------------
#define WS_F 4096                       // 256 n * 16 u floats per stage
#define XS_F 512                        // 16 u * 32 b floats per stage
#define GEMM_SMEM_BYTES ((3 * WS_F + 3 * XS_F) * 4)   // 55296 B

__global__ void __launch_bounds__(128, 4) gemm_part_kernel(const float* __restrict__ W) {
    extern __shared__ float sm[];
    float* Wsm = sm;                    // 3 stage buffers
    float* Xsm = sm + 3 * WS_F;

    const int t  = threadIdx.x;
    const int ic = blockIdx.x;
    const int jq = blockIdx.y;

    const float* Wbase = W    + (size_t)ic * IC_PER * 16384 + (size_t)jq * 4096;
    const float* Xbase = g_xT + (size_t)ic * IC_PER * (N_IU * N_B);

    ull acc0[16], acc1[16];
    #pragma unroll
    for (int p = 0; p < 16; p++) { acc0[p] = 0ULL; acc1[p] = 0ULL; }

    auto issue = [&](int s) {
        const int buf = s % 3;
        const float* wg = Wbase + (size_t)s * 16384;
        float* wd = Wsm + buf * WS_F;
        #pragma unroll
        for (int p = 0; p < 8; p++) {
            const int off  = p * 512 + t * 4;              // source float offset
            const int row  = off >> 4;                     // n row (16 floats each)
            const int slot = ((t & 3) + (row >> 1)) & 3;   // swizzled 16B granule
            cp16(su32(wd + (row << 4) + (slot << 2)), wg + off);
        }
        cp16(su32(Xsm + buf * XS_F + t * 4), Xbase + s * XS_F + t * 4);
        asm volatile("cp.async.commit_group;");
    };

    issue(0);
    issue(1);

    const int slotbase = (t >> 1) & 3;   // same for row t and row t+128

    #pragma unroll 1
    for (int s = 0; s < S_STG; s++) {
        if (s < S_STG - 1) asm volatile("cp.async.wait_group 1;");
        else               asm volatile("cp.async.wait_group 0;");
        __syncthreads();

        const int buf = s % 3;
        const float* WsB = Wsm + buf * WS_F;
        const float* XsB = Xsm + buf * XS_F;

        #pragma unroll
        for (int r4 = 0; r4 < 4; r4++) {
            const int sl = (r4 + slotbase) & 3;
            // this thread's two n-columns, 4 u's each (one conflict-free LDS.128 apiece)
            const float4 w0 = *reinterpret_cast<const float4*>(WsB + t * 16 + sl * 4);
            const float4 w1 = *reinterpret_cast<const float4*>(WsB + (t + 128) * 16 + sl * 4);
            const float wa0[4] = {w0.x, w0.y, w0.z, w0.w};
            const float wa1[4] = {w1.x, w1.y, w1.z, w1.w};
            #pragma unroll
            for (int q = 0; q < 4; q++) {
                const int r = r4 * 4 + q;                 // u index
                const ull wd0 = dup2(wa0[q]);
                const ull wd1 = dup2(wa1[q]);
                #pragma unroll
                for (int h = 0; h < 8; h++) {             // 4 b's per iter (broadcast LDS)
                    const ulonglong2 xv = *reinterpret_cast<const ulonglong2*>(XsB + r * 32 + h * 4);
                    acc0[2 * h]     = fma2(xv.x, wd0, acc0[2 * h]);
                    acc0[2 * h + 1] = fma2(xv.y, wd0, acc0[2 * h + 1]);
                    acc1[2 * h]     = fma2(xv.x, wd1, acc1[2 * h]);
                    acc1[2 * h + 1] = fma2(xv.y, wd1, acc1[2 * h + 1]);
                }
            }
        }
        if (s + 2 < S_STG) issue(s + 2);   // buf (s+2)%3 freed by this iter's barrier
    }

    // epilogue: deterministic partials, coalesced scalar rows (lanes span n)
    float* outp = &g_part[ic][0][jq * 256];
    #pragma unroll
    for (int bp = 0; bp < 16; bp++) {
        union { ull u; float2 f; } c0, c1;
        c0.u = acc0[bp]; c1.u = acc1[bp];
        outp[(size_t)(2 * bp)     * N_N + t]       = c0.f.x;
        outp[(size_t)(2 * bp + 1) * N_N + t]       = c0.f.y;
        outp[(size_t)(2 * bp)     * N_N + 128 + t] = c1.f.x;
        outp[(size_t)(2 * bp + 1) * N_N + 128 + t] = c1.f.y;
    }
}

// ---------------------------------------------------------------------------
// Kernel 3: sum 128 K-split partials + squash.
//   msq[b,k] = sum_j s[b,j,k]^2 ;  out = s * msq / ((1+msq) * sqrt(msq))
// grid (32 b, 4 k-quarters), block 256: t = j*16 + kl.
// ---------------------------------------------------------------------------
__global__ void reduce_squash_kernel(float* __restrict__ out) {
    __shared__ float smv[256];
    __shared__ float msq[16];
    const int b  = blockIdx.x;
    const int kq = blockIdx.y;
    const int t  = threadIdx.x;
    const int j  = t >> 4;
    const int kl = t & 15;
    const int n  = j * 64 + kq * 16 + kl;

    float s = 0.0f;
    #pragma unroll 16
    for (int ic = 0; ic < N_ICCH; ic++)
        s += g_part[ic][b][n];

    smv[t] = s;
    __syncthreads();
    if (t < 16) {
        float m = 0.0f;
        #pragma unroll
        for (int jj = 0; jj < 16; jj++) {
            const float v = smv[jj * 16 + t];
            m += v * v;
        }
        msq[t] = m;
    }
    __syncthreads();
    const float m = msq[kl];
    out[(size_t)b * N_N + n] = s * m / ((1.0f + m) * sqrtf(m));
}

// ---------------------------------------------------------------------------
extern "C" void kernel_launch(void* const* d_in, const int* in_sizes, int n_in,
                              void* d_out, int out_size) {
    const float* x = (const float*)d_in[0];
    const float* W = (const float*)d_in[1];
    if (n_in >= 2 && in_sizes[0] > in_sizes[1]) {   // safety: x is the smaller input
        x = (const float*)d_in[1];
        W = (const float*)d_in[0];
    }
    cudaFuncSetAttribute(gemm_part_kernel,
                         cudaFuncAttributeMaxDynamicSharedMemorySize, GEMM_SMEM_BYTES);
    transpose_x_kernel<<<dim3(N_IC / 32, N_IU), dim3(32, 8)>>>(x);
    gemm_part_kernel<<<dim3(N_ICCH, 4), 128, GEMM_SMEM_BYTES>>>(W);
    reduce_squash_kernel<<<dim3(N_B, 4), 256>>>((float*)d_out);
}